// round 8
// baseline (speedup 1.0000x reference)
#include <cuda_runtime.h>
#include <cuda_fp16.h>
#include <cstdint>

#define BATCH 64
#define HDIM 512
#define HH 262144      // HDIM*HDIM
#define NSEQ 2048
#define NFOCUS 256

// ---------------- scratch (static device globals; no runtime allocation) ----
__device__ float g_Y[(size_t)BATCH * HH];      // 64 MB (Yq then Yk)
__device__ float g_Qp[8 * BATCH * HDIM];
__device__ float g_Q[BATCH * HDIM];
__device__ float g_w[BATCH * HDIM];
__device__ float g_compat[BATCH * NSEQ];
__device__ int   g_idx[BATCH * NFOCUS];

// ======================= mma.sync helpers (HMMA path) =======================
__device__ __forceinline__ uint32_t smem_u32(const void* p) {
    uint32_t a;
    asm("{ .reg .u64 t; cvta.to.shared.u64 t, %1; cvt.u32.u64 %0, t; }"
        : "=r"(a) : "l"(p));
    return a;
}
__device__ __forceinline__ void ldsm4(uint32_t* r, uint32_t a) {
    asm volatile("ldmatrix.sync.aligned.m8n8.x4.shared.b16 {%0,%1,%2,%3}, [%4];"
                 : "=r"(r[0]), "=r"(r[1]), "=r"(r[2]), "=r"(r[3]) : "r"(a));
}
__device__ __forceinline__ void ldsm2(uint32_t* r, uint32_t a) {
    asm volatile("ldmatrix.sync.aligned.m8n8.x2.shared.b16 {%0,%1}, [%2];"
                 : "=r"(r[0]), "=r"(r[1]) : "r"(a));
}
__device__ __forceinline__ void mma16816(float* c, const uint32_t* a, const uint32_t* b) {
    asm volatile(
        "mma.sync.aligned.m16n8k16.row.col.f32.f16.f16.f32 "
        "{%0,%1,%2,%3}, {%4,%5,%6,%7}, {%8,%9}, {%0,%1,%2,%3};"
        : "+f"(c[0]), "+f"(c[1]), "+f"(c[2]), "+f"(c[3])
        : "r"(a[0]), "r"(a[1]), "r"(a[2]), "r"(a[3]), "r"(b[0]), "r"(b[1]));
}
// x ~= h1 + 2^-11 * h2  (h2 holds the residue scaled by 2^11 -> normal range)
__device__ __forceinline__ void split2h(float x, uint16_t& h1, uint16_t& h2) {
    __half a = __float2half_rn(x);
    float r = (x - __half2float(a)) * 2048.0f;
    __half b = __float2half_rn(r);
    h1 = __half_as_ushort(a);
    h2 = __half_as_ushort(b);
}
__device__ __forceinline__ void cp16(uint32_t dst, const void* src) {
    asm volatile("cp.async.cg.shared.global [%0], [%1], 16;"
                 :: "r"(dst), "l"(src) : "memory");
}
#define CP_COMMIT() asm volatile("cp.async.commit_group;" ::: "memory")
#define CP_WAIT3()  asm volatile("cp.async.wait_group 3;" ::: "memory")
#define BAR_SYNC(id, cnt)   asm volatile("bar.sync %0, %1;"   :: "r"(id), "r"(cnt) : "memory")
#define BAR_ARRIVE(id, cnt) asm volatile("bar.arrive %0, %1;" :: "r"(id), "r"(cnt) : "memory")

// ========= emulated-fp32 GEMM via 2-way fp16 split (3 HMMA products) ========
// Warp-specialized: 16 consumer warps (ldsm+mma only) + 4 producer warps
// (cp.async + convert). 4-stage raw ring, 3-stage fp16 ring, named barriers.
#define KC 32                        // k per chunk
#define NCHUNK (HDIM / KC)           // 16
#define NTILE 128                    // n per CTA
#define THREADS 640
#define NCONS 512
#define ROWB 80                      // padded fp16 smem row bytes (64B + 16 pad)
// smem byte offsets:
#define RAWW_OFF(st)   ((st) * 16384u)                 // 32k x 128n fp32
#define RAWX_OFF(st)   (65536u + (st) * 8192u)         // 64b x 32k fp32
#define FS(s)          (98304u + (s) * 30720u)
#define WS_OFF(s, l)   (FS(s) + (l) * 10240u)          // 128n x 32k fp16 (ROWB)
#define XS_OFF(s, l)   (FS(s) + 20480u + (l) * 5120u)  // 64b x 32k fp16 (ROWB)
#define SMEM_BYTES 190464
// named barriers: FULL_s = 1+s, EMPTY_s = 4+s (s=0..2), producer-internal = 7

__global__ __launch_bounds__(THREADS, 1) void gemm_mma(
    const float* __restrict__ X, const float* __restrict__ W,
    const float* __restrict__ bias)
{
    extern __shared__ __align__(16) char smem_raw[];
    const uint32_t sb = smem_u32(smem_raw);
    const int tid = threadIdx.x;
    const int wid = tid >> 5, lane = tid & 31;
    const int n0 = blockIdx.x * NTILE;

    if (wid < 16) {
        // ================= CONSUMERS: ldsm + mma only =================
        const int mpair = wid & 1;
        const int noct  = wid >> 1;          // 0..7

        float lo[2][2][4], hi[2][2][4];
        #pragma unroll
        for (int m = 0; m < 2; m++)
            #pragma unroll
            for (int j = 0; j < 2; j++)
                #pragma unroll
                for (int q = 0; q < 4; q++) { lo[m][j][q] = 0.f; hi[m][j][q] = 0.f; }

        const uint32_t a_row = (uint32_t)(32 * mpair + (lane & 15)) * ROWB + ((lane >> 4) << 4);
        const uint32_t b_row = (uint32_t)(noct * 16 + (lane & 7)) * ROWB + (((lane >> 3) & 1) << 4);

        for (int kc = 0; kc < NCHUNK; kc++) {
            const int s = kc % 3;
            BAR_SYNC(1 + s, THREADS);        // wait stage full

            #pragma unroll
            for (int ks = 0; ks < 2; ks++) {
                uint32_t b1[2][2], b2[2][2], a1[2][4], a2[2][4];
                #pragma unroll
                for (int j = 0; j < 2; j++) {
                    ldsm2(b1[j], sb + WS_OFF(s, 0) + b_row + (uint32_t)j * (8 * ROWB) + ks * 32);
                    ldsm2(b2[j], sb + WS_OFF(s, 1) + b_row + (uint32_t)j * (8 * ROWB) + ks * 32);
                }
                #pragma unroll
                for (int m = 0; m < 2; m++) {
                    ldsm4(a1[m], sb + XS_OFF(s, 0) + a_row + (uint32_t)m * (16 * ROWB) + ks * 32);
                    ldsm4(a2[m], sb + XS_OFF(s, 1) + a_row + (uint32_t)m * (16 * ROWB) + ks * 32);
                }
                #pragma unroll
                for (int m = 0; m < 2; m++)
                    #pragma unroll
                    for (int j = 0; j < 2; j++) mma16816(lo[m][j], a1[m], b1[j]);
                #pragma unroll
                for (int m = 0; m < 2; m++)
                    #pragma unroll
                    for (int j = 0; j < 2; j++) mma16816(hi[m][j], a1[m], b2[j]);
                #pragma unroll
                for (int m = 0; m < 2; m++)
                    #pragma unroll
                    for (int j = 0; j < 2; j++) mma16816(hi[m][j], a2[m], b1[j]);
            }

            BAR_ARRIVE(4 + s, THREADS);      // signal stage empty
        }

        // ---- epilogue: Y = lo + hi/2048 + bias ----
        const float sc = 1.0f / 2048.0f;
        const int ncol = n0 + noct * 16 + (lane & 3) * 2;
        #pragma unroll
        for (int m = 0; m < 2; m++) {
            const int brow = 32 * mpair + 16 * m + (lane >> 2);
            #pragma unroll
            for (int j = 0; j < 2; j++) {
                const int n = ncol + j * 8;
                const float2 bz = *(const float2*)&bias[n];
                float2 o0 = make_float2(fmaf(hi[m][j][0], sc, lo[m][j][0]) + bz.x,
                                        fmaf(hi[m][j][1], sc, lo[m][j][1]) + bz.y);
                float2 o1 = make_float2(fmaf(hi[m][j][2], sc, lo[m][j][2]) + bz.x,
                                        fmaf(hi[m][j][3], sc, lo[m][j][3]) + bz.y);
                *(float2*)&g_Y[(size_t)brow * HH + n]       = o0;
                *(float2*)&g_Y[(size_t)(brow + 8) * HH + n] = o1;
            }
        }
    } else {
        // ================= PRODUCERS: cp.async + convert =================
        const int ptid = tid - NCONS;                 // 0..127
        const int wseg = ptid & 31;                   // W: 16B n-seg
        const int wk4  = ptid >> 5;                   // W: k-subrow group
        const int xb   = ptid >> 1, xkh = ptid & 1;   // X convert: batch row, k-half

        #define ISSUE(chunk) do {                                                   \
            const int _st = (chunk) & 3;                                            \
            const uint32_t wdst = sb + RAWW_OFF(_st);                               \
            const float* wsrc = W + (size_t)((chunk) * KC) * HH + n0;               \
            _Pragma("unroll")                                                       \
            for (int i = 0; i < 8; i++) {                                           \
                const int k = i * 4 + wk4;                                          \
                cp16(wdst + (uint32_t)k * 512u + (uint32_t)wseg * 16u,              \
                     wsrc + (size_t)k * HH + wseg * 4);                             \
            }                                                                       \
            _Pragma("unroll")                                                       \
            for (int i = 0; i < 4; i++) {                                           \
                const int b = i * 16 + (ptid >> 3);                                 \
                const int ks = ptid & 7;                                            \
                cp16(sb + RAWX_OFF(_st) + (uint32_t)b * 128u + (uint32_t)ks * 16u,  \
                     X + (size_t)b * HDIM + (chunk) * KC + ks * 4);                 \
            }                                                                       \
        } while (0)

        ISSUE(0); CP_COMMIT();
        ISSUE(1); CP_COMMIT();
        ISSUE(2); CP_COMMIT();

        for (int kc = 0; kc < NCHUNK; kc++) {
            if (kc + 3 < NCHUNK) ISSUE(kc + 3);
            CP_COMMIT();
            CP_WAIT3();                      // chunk kc raw complete (this thread)
            BAR_SYNC(7, 128);                // cross-producer visibility

            const int s = kc % 3;
            if (kc >= 3) BAR_SYNC(4 + s, THREADS);   // wait stage empty

            // ---- convert W: thread owns fp16 row n=ptid, k=0..31 ----
            {
                const char* rw = smem_raw + RAWW_OFF(kc & 3);
                uint32_t u1[16], u2[16];
                #pragma unroll
                for (int kk = 0; kk < 16; kk++) {
                    float x0 = *(const float*)(rw + (uint32_t)(2 * kk) * 512u + (uint32_t)ptid * 4u);
                    float x1 = *(const float*)(rw + (uint32_t)(2 * kk + 1) * 512u + (uint32_t)ptid * 4u);
                    uint16_t a1v, a2v, c1v, c2v;
                    split2h(x0, a1v, a2v);
                    split2h(x1, c1v, c2v);
                    u1[kk] = (uint32_t)a1v | ((uint32_t)c1v << 16);
                    u2[kk] = (uint32_t)a2v | ((uint32_t)c2v << 16);
                }
                const uint32_t rb = (uint32_t)ptid * ROWB;
                #pragma unroll
                for (int q = 0; q < 4; q++) {
                    asm volatile("st.shared.v4.b32 [%0], {%1,%2,%3,%4};" ::
                        "r"(sb + WS_OFF(s, 0) + rb + q * 16),
                        "r"(u1[4*q]), "r"(u1[4*q+1]), "r"(u1[4*q+2]), "r"(u1[4*q+3]) : "memory");
                    asm volatile("st.shared.v4.b32 [%0], {%1,%2,%3,%4};" ::
                        "r"(sb + WS_OFF(s, 1) + rb + q * 16),
                        "r"(u2[4*q]), "r"(u2[4*q+1]), "r"(u2[4*q+2]), "r"(u2[4*q+3]) : "memory");
                }
            }
            // ---- convert X: thread owns fp16 half-row (b=xb, k-half=xkh) ----
            {
                const char* rx = smem_raw + RAWX_OFF(kc & 3);
                uint32_t v1[8], v2[8];
                #pragma unroll
                for (int i = 0; i < 4; i++) {
                    float4 xv = *(const float4*)(rx + (uint32_t)xb * 128u + (uint32_t)xkh * 64u + i * 16u);
                    uint16_t a1v, a2v, c1v, c2v;
                    split2h(xv.x, a1v, a2v); split2h(xv.y, c1v, c2v);
                    v1[i*2]   = (uint32_t)a1v | ((uint32_t)c1v << 16);
                    v2[i*2]   = (uint32_t)a2v | ((uint32_t)c2v << 16);
                    split2h(xv.z, a1v, a2v); split2h(xv.w, c1v, c2v);
                    v1[i*2+1] = (uint32_t)a1v | ((uint32_t)c1v << 16);
                    v2[i*2+1] = (uint32_t)a2v | ((uint32_t)c2v << 16);
                }
                const uint32_t xrb = (uint32_t)xb * ROWB + xkh * 32;
                asm volatile("st.shared.v4.b32 [%0], {%1,%2,%3,%4};" ::
                    "r"(sb + XS_OFF(s, 0) + xrb), "r"(v1[0]), "r"(v1[1]), "r"(v1[2]), "r"(v1[3]) : "memory");
                asm volatile("st.shared.v4.b32 [%0], {%1,%2,%3,%4};" ::
                    "r"(sb + XS_OFF(s, 0) + xrb + 16), "r"(v1[4]), "r"(v1[5]), "r"(v1[6]), "r"(v1[7]) : "memory");
                asm volatile("st.shared.v4.b32 [%0], {%1,%2,%3,%4};" ::
                    "r"(sb + XS_OFF(s, 1) + xrb), "r"(v2[0]), "r"(v2[1]), "r"(v2[2]), "r"(v2[3]) : "memory");
                asm volatile("st.shared.v4.b32 [%0], {%1,%2,%3,%4};" ::
                    "r"(sb + XS_OFF(s, 1) + xrb + 16), "r"(v2[4]), "r"(v2[5]), "r"(v2[6]), "r"(v2[7]) : "memory");
            }

            BAR_ARRIVE(1 + s, THREADS);      // signal stage full
        }
        #undef ISSUE
    }
}

// ---------------- Qpart[s,b,k] = sum_{h in slice s} x[b,h] * Y[b, h*H + k] --
__global__ void contract_q(const float* __restrict__ X) {
    const int b = blockIdx.y, s = blockIdx.x;
    const int k = threadIdx.x;  // 512
    __shared__ float xs[64];
    if (k < 64) xs[k] = X[b * HDIM + s * 64 + k];
    __syncthreads();
    const float* Yb = g_Y + (size_t)b * HH + (size_t)s * 64 * HDIM + k;
    float a0 = 0.f, a1 = 0.f, a2 = 0.f, a3 = 0.f;
    #pragma unroll
    for (int hh = 0; hh < 64; hh += 4) {
        a0 = fmaf(xs[hh + 0], Yb[(hh + 0) * HDIM], a0);
        a1 = fmaf(xs[hh + 1], Yb[(hh + 1) * HDIM], a1);
        a2 = fmaf(xs[hh + 2], Yb[(hh + 2) * HDIM], a2);
        a3 = fmaf(xs[hh + 3], Yb[(hh + 3) * HDIM], a3);
    }
    g_Qp[(s * BATCH + b) * HDIM + k] = (a0 + a1) + (a2 + a3);
}

__global__ void reduce_q() {
    const int b = blockIdx.x, k = threadIdx.x;
    float v = 0.f;
    #pragma unroll
    for (int s = 0; s < 8; s++) v += g_Qp[(s * BATCH + b) * HDIM + k];
    g_Q[b * HDIM + k] = v;
}

// ---------------- w[b,h] = < Y[b, h*H : h*H+H] , Q[b,:] > -------------------
__global__ void contract_w() {
    const int b = blockIdx.y;
    const int warp = threadIdx.x >> 5, lane = threadIdx.x & 31;
    const int h = blockIdx.x * 8 + warp;
    __shared__ float qs[HDIM];
    for (int i = threadIdx.x; i < HDIM; i += 256) qs[i] = g_Q[b * HDIM + i];
    __syncthreads();
    const float* Yb = g_Y + (size_t)b * HH + (size_t)h * HDIM;
    float acc = 0.f;
    #pragma unroll
    for (int s2 = 0; s2 < 4; s2++) {
        const int i4 = lane + s2 * 32;
        float4 y = *(const float4*)&Yb[i4 * 4];
        float4 q = *(const float4*)&qs[i4 * 4];
        acc += y.x * q.x + y.y * q.y + y.z * q.z + y.w * q.w;
    }
    #pragma unroll
    for (int off = 16; off; off >>= 1) acc += __shfl_xor_sync(~0u, acc, off);
    if (lane == 0) g_w[b * HDIM + h] = acc;
}

// ---------------- compat[b,n] = norm * < ve[b,n,:], w[b,:] > ----------------
__global__ void compat_k(const float* __restrict__ ve) {
    const int b = blockIdx.y;
    const int warp = threadIdx.x >> 5, lane = threadIdx.x & 31;
    const int n = blockIdx.x * 8 + warp;
    __shared__ float ws[HDIM];
    for (int i = threadIdx.x; i < HDIM; i += 256) ws[i] = g_w[b * HDIM + i];
    __syncthreads();
    const float* v = ve + ((size_t)b * NSEQ + n) * HDIM;
    float acc = 0.f;
    #pragma unroll
    for (int s2 = 0; s2 < 4; s2++) {
        const int i4 = lane + s2 * 32;
        float4 y = *(const float4*)&v[i4 * 4];
        float4 q = *(const float4*)&ws[i4 * 4];
        acc += y.x * q.x + y.y * q.y + y.z * q.z + y.w * q.w;
    }
    #pragma unroll
    for (int off = 16; off; off >>= 1) acc += __shfl_xor_sync(~0u, acc, off);
    if (lane == 0) g_compat[b * NSEQ + n] = acc * 0.04419417382415922f;
}

// ---------------- per-batch ranking with fp32-exp flush boundary ------------
__global__ __launch_bounds__(1024) void topk_k() {
    __shared__ unsigned sk[NSEQ];
    __shared__ int      si[NSEQ];
    __shared__ float    redf[32];
    const int b = blockIdx.x, t = threadIdx.x;
    const int lane = t & 31, warp = t >> 5;

    const float c0 = g_compat[b * NSEQ + t];
    const float c1 = g_compat[b * NSEQ + t + 1024];

    float m = fmaxf(c0, c1);
    #pragma unroll
    for (int o = 16; o; o >>= 1) m = fmaxf(m, __shfl_xor_sync(~0u, m, o));
    if (lane == 0) redf[warp] = m;
    __syncthreads();
    float mx = redf[0];
    #pragma unroll
    for (int i = 1; i < 32; i++) mx = fmaxf(mx, redf[i]);

    auto mkkey = [&](float c) -> unsigned {
        float d = c - mx;
        if (d < -87.33654785f) return 0u;
        unsigned u = __float_as_uint(c);
        return (u & 0x80000000u) ? ~u : (u | 0x80000000u);
    };
    sk[t]        = mkkey(c0);  si[t]        = t;
    sk[t + 1024] = mkkey(c1);  si[t + 1024] = t + 1024;

    for (int k = 2; k <= NSEQ; k <<= 1) {
        for (int j = k >> 1; j > 0; j >>= 1) {
            __syncthreads();
            #pragma unroll
            for (int half = 0; half < 2; half++) {
                const int i = half * 1024 + t;
                const int ixj = i ^ j;
                if (ixj > i) {
                    const bool desc = ((i & k) == 0);
                    unsigned ki = sk[i], kj = sk[ixj];
                    int      ii = si[i], ij = si[ixj];
                    const bool jBeforeI = (kj > ki) || (kj == ki && ij < ii);
                    if (desc ? jBeforeI : !jBeforeI) {
                        sk[i] = kj; sk[ixj] = ki;
                        si[i] = ij; si[ixj] = ii;
                    }
                }
            }
        }
    }
    __syncthreads();
    if (t < NFOCUS) g_idx[b * NFOCUS + t] = si[t];
}

// ---------------- gather: out[b,r,:] = ve[b, idx[b,r], :] -------------------
__global__ void gather_k(const float* __restrict__ ve, float* __restrict__ out) {
    const int b = blockIdx.y, r = blockIdx.x;
    const int idx = g_idx[b * NFOCUS + r];
    const float4* src = (const float4*)(ve + ((size_t)b * NSEQ + idx) * HDIM);
    float4* dst = (float4*)(out + ((size_t)b * NFOCUS + r) * HDIM);
    dst[threadIdx.x] = src[threadIdx.x];
}

// ---------------- launch ----------------------------------------------------
extern "C" void kernel_launch(void* const* d_in, const int* in_sizes, int n_in,
                              void* d_out, int out_size) {
    const float* vs = (const float*)d_in[0];   // (64, 1, 512)
    const float* ve = (const float*)d_in[1];   // (64, 2048, 512)
    const float* Wq = (const float*)d_in[2];   // (512, 262144)
    const float* bq = (const float*)d_in[3];   // (262144,)
    const float* Wk = (const float*)d_in[4];   // (512, 262144)
    const float* bk = (const float*)d_in[5];   // (262144,)
    float* out = (float*)d_out;                // (64, 256, 512)

    cudaFuncSetAttribute(gemm_mma, cudaFuncAttributeMaxDynamicSharedMemorySize, SMEM_BYTES);

    gemm_mma<<<HH / NTILE, THREADS, SMEM_BYTES>>>(vs, Wq, bq);
    contract_q<<<dim3(8, BATCH), 512>>>(vs);
    reduce_q<<<BATCH, HDIM>>>();

    gemm_mma<<<HH / NTILE, THREADS, SMEM_BYTES>>>(vs, Wk, bk);
    contract_w<<<dim3(64, BATCH), 256>>>();

    compat_k<<<dim3(NSEQ / 8, BATCH), 256>>>(ve);
    topk_k<<<BATCH, 1024>>>();
    gather_k<<<dim3(NFOCUS, BATCH), 128>>>(ve, out);
}